// round 17
// baseline (speedup 1.0000x reference)
#include <cuda_runtime.h>
#include <cuda_bf16.h>
#include <cstdint>

#define N_NODES_MAX 100000
#define D 64
#define OUT 64
#define LN_EPS 1e-5f

// Scratch: neighbor_sum accumulator [N, D]
__device__ __align__(16) float g_nsum[N_NODES_MAX * D];

// ---------------------------------------------------------------------------
// Kernel 1: scatter-add (R12-proven, unroll-4 MLP, red.global.add.v4.f32)
// ---------------------------------------------------------------------------
__global__ void __launch_bounds__(256) scatter_kernel(
    const float4* __restrict__ x4,
    const void* __restrict__ ei_raw,
    int n_edges, int n_nodes) {

    const long long* ei64 = reinterpret_cast<const long long*>(ei_raw);
    const int*       ei32 = reinterpret_cast<const int*>(ei_raw);

    int bad = 0;
    {
        int nw = n_edges / 2;
        if (nw > 256) nw = 256;
        if ((int)threadIdx.x < nw) {
            long long v = ei64[threadIdx.x];
            bad = (v < 0 || v >= (long long)n_nodes) ? 1 : 0;
        }
    }
    const int is64 = !__syncthreads_or(bad);

    const int t   = blockIdx.x * blockDim.x + threadIdx.x;
    const int sub = t & 15;
    const int grp = t >> 4;
    const int ngrp = (gridDim.x * blockDim.x) >> 4;
    float4* __restrict__ nsum4 = reinterpret_cast<float4*>(g_nsum);
    const int nchunks = n_edges >> 2;

    if (is64) {
        for (int c = grp; c < nchunks; c += ngrp) {
            const int e = c * 4;
            longlong2 r01 = *reinterpret_cast<const longlong2*>(ei64 + e);
            longlong2 r23 = *reinterpret_cast<const longlong2*>(ei64 + e + 2);
            longlong2 c01 = *reinterpret_cast<const longlong2*>(ei64 + n_edges + e);
            longlong2 c23 = *reinterpret_cast<const longlong2*>(ei64 + n_edges + e + 2);
            float4 v0 = x4[r01.x * 16 + sub];
            float4 v1 = x4[r01.y * 16 + sub];
            float4 v2 = x4[r23.x * 16 + sub];
            float4 v3 = x4[r23.y * 16 + sub];
            asm volatile("red.global.add.v4.f32 [%0], {%1, %2, %3, %4};"
                         :: "l"(&nsum4[c01.x * 16 + sub]),
                            "f"(v0.x), "f"(v0.y), "f"(v0.z), "f"(v0.w) : "memory");
            asm volatile("red.global.add.v4.f32 [%0], {%1, %2, %3, %4};"
                         :: "l"(&nsum4[c01.y * 16 + sub]),
                            "f"(v1.x), "f"(v1.y), "f"(v1.z), "f"(v1.w) : "memory");
            asm volatile("red.global.add.v4.f32 [%0], {%1, %2, %3, %4};"
                         :: "l"(&nsum4[c23.x * 16 + sub]),
                            "f"(v2.x), "f"(v2.y), "f"(v2.z), "f"(v2.w) : "memory");
            asm volatile("red.global.add.v4.f32 [%0], {%1, %2, %3, %4};"
                         :: "l"(&nsum4[c23.y * 16 + sub]),
                            "f"(v3.x), "f"(v3.y), "f"(v3.z), "f"(v3.w) : "memory");
        }
        for (int e = (nchunks << 2) + grp; e < n_edges; e += ngrp) {
            long long row = ei64[e];
            long long col = ei64[n_edges + e];
            float4 v = x4[row * 16 + sub];
            asm volatile("red.global.add.v4.f32 [%0], {%1, %2, %3, %4};"
                         :: "l"(&nsum4[col * 16 + sub]),
                            "f"(v.x), "f"(v.y), "f"(v.z), "f"(v.w) : "memory");
        }
    } else {
        for (int c = grp; c < nchunks; c += ngrp) {
            const int e = c * 4;
            int4 rr = *reinterpret_cast<const int4*>(ei32 + e);
            int4 cc = *reinterpret_cast<const int4*>(ei32 + n_edges + e);
            float4 v0 = x4[(long long)rr.x * 16 + sub];
            float4 v1 = x4[(long long)rr.y * 16 + sub];
            float4 v2 = x4[(long long)rr.z * 16 + sub];
            float4 v3 = x4[(long long)rr.w * 16 + sub];
            asm volatile("red.global.add.v4.f32 [%0], {%1, %2, %3, %4};"
                         :: "l"(&nsum4[(long long)cc.x * 16 + sub]),
                            "f"(v0.x), "f"(v0.y), "f"(v0.z), "f"(v0.w) : "memory");
            asm volatile("red.global.add.v4.f32 [%0], {%1, %2, %3, %4};"
                         :: "l"(&nsum4[(long long)cc.y * 16 + sub]),
                            "f"(v1.x), "f"(v1.y), "f"(v1.z), "f"(v1.w) : "memory");
            asm volatile("red.global.add.v4.f32 [%0], {%1, %2, %3, %4};"
                         :: "l"(&nsum4[(long long)cc.z * 16 + sub]),
                            "f"(v2.x), "f"(v2.y), "f"(v2.z), "f"(v2.w) : "memory");
            asm volatile("red.global.add.v4.f32 [%0], {%1, %2, %3, %4};"
                         :: "l"(&nsum4[(long long)cc.w * 16 + sub]),
                            "f"(v3.x), "f"(v3.y), "f"(v3.z), "f"(v3.w) : "memory");
        }
        for (int e = (nchunks << 2) + grp; e < n_edges; e += ngrp) {
            long long row = ei32[e];
            long long col = ei32[n_edges + e];
            float4 v = x4[row * 16 + sub];
            asm volatile("red.global.add.v4.f32 [%0], {%1, %2, %3, %4};"
                         :: "l"(&nsum4[col * 16 + sub]),
                            "f"(v.x), "f"(v.y), "f"(v.z), "f"(v.w) : "memory");
        }
    }
}

// ---------------------------------------------------------------------------
// Kernel 2: mma.sync bf16 (3-pass hi/lo) GEMM + bias + LayerNorm.
// TILE 64 nodes x 64 outs, K=128. 8 warps as 4(m) x 2(n); warp tile 16x32.
// smem 64KB + 1KB exchange -> 3 blocks/SM.
// LN rows span 2 warps -> quad-shfl partial + smem exchange (8 warps x 8 qr
// x float4 = 1024B — the R16 crash was this buffer sized at 512B).
// Fragment/swizzle layout identical to validated R15.
// ---------------------------------------------------------------------------
#define TILE_N 64
#define GTHR   256

// smem layout (bytes)
#define SM_AHI  0          // 2 halves x 8KB  (64 rows x 64k bf16 per half)
#define SM_ALO  16384      // 2 halves x 8KB
#define SM_WHI  32768      // 2 halves x 8KB  (64 outs x 64k bf16 per half)
#define SM_WLO  49152      // 2 halves x 8KB
#define SM_RED  65536      // [8 warps][8 qr] float4 partials = 1024B
#define SM_TOT  66560

__device__ __forceinline__ uint32_t smem_u32(const void* p) {
    uint32_t a;
    asm("{ .reg .u64 t; cvta.to.shared.u64 t, %1; cvt.u32.u64 %0, t; }"
        : "=r"(a) : "l"(p));
    return a;
}
__device__ __forceinline__ uint32_t sw128(uint32_t o) { return o ^ ((o >> 3) & 0x70); }

__device__ __forceinline__ unsigned pack_bf16x2(float lo_f, float hi_f) {
    __nv_bfloat16 a = __float2bfloat16(lo_f);
    __nv_bfloat16 c = __float2bfloat16(hi_f);
    return ((unsigned)__bfloat16_as_ushort(c) << 16) | (unsigned)__bfloat16_as_ushort(a);
}

__device__ __forceinline__ void ldmx4(uint32_t addr, uint32_t* r) {
    asm volatile("ldmatrix.sync.aligned.m8n8.x4.shared.b16 {%0,%1,%2,%3}, [%4];"
                 : "=r"(r[0]), "=r"(r[1]), "=r"(r[2]), "=r"(r[3]) : "r"(addr));
}
__device__ __forceinline__ void mma_bf16(float* c, const uint32_t* a,
                                         uint32_t b0, uint32_t b1) {
    asm volatile(
        "mma.sync.aligned.m16n8k16.row.col.f32.bf16.bf16.f32 "
        "{%0,%1,%2,%3}, {%4,%5,%6,%7}, {%8,%9}, {%0,%1,%2,%3};"
        : "+f"(c[0]), "+f"(c[1]), "+f"(c[2]), "+f"(c[3])
        : "r"(a[0]), "r"(a[1]), "r"(a[2]), "r"(a[3]), "r"(b0), "r"(b1));
}

__global__ void __launch_bounds__(GTHR, 3) gemm_mma_ln_kernel(
    const float4* __restrict__ x4,
    const float4* __restrict__ W4,   // [128][16] float4  (W row-major [128][64])
    const float*  __restrict__ b,
    const float*  __restrict__ gamma,
    const float*  __restrict__ beta,
    float2* __restrict__ out2,
    int n_nodes) {

    extern __shared__ char smem[];
    const uint32_t sbase = smem_u32(smem);
    const int tid = threadIdx.x;
    const int wid = tid >> 5;
    const int lid = tid & 31;
    const int mw  = wid & 3;     // row group: rows 16*mw .. 16*mw+15
    const int nw  = wid >> 2;    // col group: cols 32*nw .. 32*nw+31
    const int node_base = blockIdx.x * TILE_N;

    // ---- stage A (hi/lo bf16, k-major, SW128 halves) ----
    {
        const float4* nsum4 = reinterpret_cast<const float4*>(g_nsum);
        #pragma unroll
        for (int it = 0; it < 8; it++) {
            int idx = it * GTHR + tid;     // 0..2047
            int r = idx & 31;              // k-quad 0..31
            int n = idx >> 5;              // node row 0..63
            int gn = node_base + n;
            float4 v = make_float4(0.f, 0.f, 0.f, 0.f);
            if (gn < n_nodes)
                v = (r < 16) ? x4[(long long)gn * 16 + r]
                             : nsum4[(long long)gn * 16 + (r - 16)];
            float hx = __bfloat162float(__float2bfloat16(v.x));
            float hy = __bfloat162float(__float2bfloat16(v.y));
            float hz = __bfloat162float(__float2bfloat16(v.z));
            float hw = __bfloat162float(__float2bfloat16(v.w));
            uint2 hi = make_uint2(pack_bf16x2(hx, hy), pack_bf16x2(hz, hw));
            uint2 lo = make_uint2(pack_bf16x2(v.x - hx, v.y - hy),
                                  pack_bf16x2(v.z - hz, v.w - hw));
            int h = r >> 4;
            uint32_t off = sw128((uint32_t)(n * 128 + (r & 15) * 8));
            *reinterpret_cast<uint2*>(smem + SM_AHI + h * 8192 + off) = hi;
            *reinterpret_cast<uint2*>(smem + SM_ALO + h * 8192 + off) = lo;
        }
    }
    // ---- stage W^T (hi/lo bf16) ----
    {
        #pragma unroll
        for (int it = 0; it < 8; it++) {
            int idx = it * GTHR + tid;     // 0..2047
            int k = idx >> 4;              // 0..127
            int n4 = idx & 15;
            float4 w = W4[idx];
            const float ww[4] = {w.x, w.y, w.z, w.w};
            int h = k >> 6;
            int klocal = k & 63;
            #pragma unroll
            for (int j = 0; j < 4; j++) {
                int n = 4 * n4 + j;
                float hv = __bfloat162float(__float2bfloat16(ww[j]));
                uint32_t off = sw128((uint32_t)(n * 128 + klocal * 2));
                *reinterpret_cast<__nv_bfloat16*>(smem + SM_WHI + h * 8192 + off) =
                    __float2bfloat16(ww[j]);
                *reinterpret_cast<__nv_bfloat16*>(smem + SM_WLO + h * 8192 + off) =
                    __float2bfloat16(ww[j] - hv);
            }
        }
    }
    __syncthreads();

    // ---- mainloop: warp (mw, nw) owns rows 16mw..+15, cols 32nw..+31 ----
    const int m_base = mw * 16;
    float acc[4][4];
    #pragma unroll
    for (int nt = 0; nt < 4; nt++)
        #pragma unroll
        for (int j = 0; j < 4; j++) acc[nt][j] = 0.f;

    const int l15 = lid & 15;
    const int lh  = lid >> 4;

    #pragma unroll 1
    for (int pass = 0; pass < 3; pass++) {
        const uint32_t aMat = sbase + ((pass == 1) ? SM_ALO : SM_AHI);
        const uint32_t wMat = sbase + ((pass == 2) ? SM_WLO : SM_WHI);
        #pragma unroll
        for (int s = 0; s < 8; s++) {
            const int h = s >> 2;
            const int klb = (s & 3) * 32;
            uint32_t a[4];
            {
                uint32_t off = sw128((uint32_t)((m_base + l15) * 128 + klb + lh * 16));
                ldmx4(aMat + h * 8192 + off, a);
            }
            uint32_t bf[2][4];
            #pragma unroll
            for (int ql = 0; ql < 2; ql++) {
                int q = 2 * nw + ql;
                uint32_t off = sw128((uint32_t)((q * 16 + l15) * 128 + klb + lh * 16));
                ldmx4(wMat + h * 8192 + off, bf[ql]);
            }
            #pragma unroll
            for (int nt = 0; nt < 4; nt++) {
                const int ql = nt >> 1;
                uint32_t b0 = (nt & 1) ? bf[ql][1] : bf[ql][0];
                uint32_t b1 = (nt & 1) ? bf[ql][3] : bf[ql][2];
                mma_bf16(acc[nt], a, b0, b1);
            }
        }
    }

    // ---- epilogue: bias + cross-warp LN + store ----
    // frag: c0,c1 -> row qr, cols 32nw+8nt+2qc,+1 ; c2,c3 -> row qr+8
    const int qr = lid >> 2;
    const int qc = lid & 3;
    const float2* b2 = reinterpret_cast<const float2*>(b);
    const float2* g2 = reinterpret_cast<const float2*>(gamma);
    const float2* e2 = reinterpret_cast<const float2*>(beta);

    float s0 = 0.f, ss0 = 0.f, s1 = 0.f, ss1 = 0.f;
    #pragma unroll
    for (int nt = 0; nt < 4; nt++) {
        float2 bb = __ldg(b2 + 16 * nw + 4 * nt + qc);
        acc[nt][0] += bb.x;  acc[nt][1] += bb.y;
        acc[nt][2] += bb.x;  acc[nt][3] += bb.y;
        s0  += acc[nt][0] + acc[nt][1];
        ss0 += acc[nt][0] * acc[nt][0] + acc[nt][1] * acc[nt][1];
        s1  += acc[nt][2] + acc[nt][3];
        ss1 += acc[nt][2] * acc[nt][2] + acc[nt][3] * acc[nt][3];
    }
    // quad butterfly -> 32-col partials broadcast within each row-quad
    #pragma unroll
    for (int m = 1; m < 4; m <<= 1) {
        s0  += __shfl_xor_sync(0xFFFFFFFFu, s0,  m);
        ss0 += __shfl_xor_sync(0xFFFFFFFFu, ss0, m);
        s1  += __shfl_xor_sync(0xFFFFFFFFu, s1,  m);
        ss1 += __shfl_xor_sync(0xFFFFFFFFu, ss1, m);
    }
    // exchange with partner warp (same mw, other nw)
    float4* red = reinterpret_cast<float4*>(smem + SM_RED);
    if (qc == 0)
        red[(mw * 2 + nw) * 8 + qr] = make_float4(s0, ss0, s1, ss1);
    __syncthreads();
    {
        float4 p = red[(mw * 2 + (1 - nw)) * 8 + qr];
        s0 += p.x; ss0 += p.y; s1 += p.z; ss1 += p.w;
    }

    const float inv64 = 1.0f / 64.0f;
    float mu0 = s0 * inv64, var0 = ss0 * inv64 - mu0 * mu0;
    float mu1 = s1 * inv64, var1 = ss1 * inv64 - mu1 * mu1;
    float rs0 = rsqrtf(var0 + LN_EPS);
    float rs1 = rsqrtf(var1 + LN_EPS);

    const int gr0 = node_base + m_base + qr;
    const int gr1 = gr0 + 8;
    #pragma unroll
    for (int nt = 0; nt < 4; nt++) {
        float2 gg = __ldg(g2 + 16 * nw + 4 * nt + qc);
        float2 ee = __ldg(e2 + 16 * nw + 4 * nt + qc);
        if (gr0 < n_nodes) {
            float2 o;
            o.x = (acc[nt][0] - mu0) * rs0 * gg.x + ee.x;
            o.y = (acc[nt][1] - mu0) * rs0 * gg.y + ee.y;
            out2[(long long)gr0 * 32 + 16 * nw + 4 * nt + qc] = o;
        }
        if (gr1 < n_nodes) {
            float2 o;
            o.x = (acc[nt][2] - mu1) * rs1 * gg.x + ee.x;
            o.y = (acc[nt][3] - mu1) * rs1 * gg.y + ee.y;
            out2[(long long)gr1 * 32 + 16 * nw + 4 * nt + qc] = o;
        }
    }
}

// ---------------------------------------------------------------------------
// launch
// ---------------------------------------------------------------------------
extern "C" void kernel_launch(void* const* d_in, const int* in_sizes, int n_in,
                              void* d_out, int out_size) {
    const float* x     = (const float*)d_in[0];
    const void*  ei    = d_in[1];
    const float* W     = (const float*)d_in[2];
    const float* b     = (const float*)d_in[3];
    const float* gamma = (const float*)d_in[4];
    const float* beta  = (const float*)d_in[5];
    float* out = (float*)d_out;

    const int n_nodes = in_sizes[0] / D;      // 100000
    const int n_edges = in_sizes[1] / 2;      // 1000000

    static void* nsum_ptr = nullptr;
    if (!nsum_ptr) {
        cudaGetSymbolAddress(&nsum_ptr, g_nsum);
        cudaFuncSetAttribute(gemm_mma_ln_kernel,
                             cudaFuncAttributeMaxDynamicSharedMemorySize, SM_TOT);
    }

    // 0: zero accumulator
    cudaMemsetAsync(nsum_ptr, 0, (size_t)n_nodes * D * sizeof(float), 0);

    // 1: scatter
    scatter_kernel<<<2368, 256>>>((const float4*)x, ei, n_edges, n_nodes);

    // 2: tensor-core bf16 (3-pass) GEMM + LayerNorm, 3 blocks/SM
    int gemm_blocks = (n_nodes + TILE_N - 1) / TILE_N;
    gemm_mma_ln_kernel<<<gemm_blocks, GTHR, SM_TOT>>>(
        (const float4*)x, (const float4*)W, b, gamma, beta,
        (float2*)out, n_nodes);
}